// round 11
// baseline (speedup 1.0000x reference)
#include <cuda_runtime.h>
#include <cuda_fp16.h>
#include <cstdint>

#define NPIX    65536
#define HW      1024
#define DIM     64
#define KCODES  512
#define TILE_M  256          // pixels per tile
#define NTILES  256
#define GRID    148
#define THREADS 256          // 8 warps, each owns 32 pixel rows

// smem byte offsets; rows padded to 144B (72 halves) -> conflict-free ldmatrix
#define ROWB    144
#define OFF_AHI 0
#define OFF_ALO (OFF_AHI + TILE_M * ROWB)    // 36864
#define OFF_BHI (OFF_ALO + TILE_M * ROWB)    // 73728
#define OFF_BLO (OFF_BHI + KCODES * ROWB)    // 147456
#define OFF_E2  (OFF_BLO + KCODES * ROWB)    // 221184
#define OFF_KW  (OFF_E2 + KCODES * 4)        // 223232
#define SMEM_SZ (OFF_KW + TILE_M * 4)        // 224256

static __device__ __forceinline__ uint32_t s2u(const void* p) {
    uint32_t a;
    asm("{ .reg .u64 t; cvta.to.shared.u64 t, %1; cvt.u32.u64 %0, t; }"
        : "=r"(a) : "l"(p));
    return a;
}

#define LDSM_X4(r, addr) \
    asm volatile("ldmatrix.sync.aligned.m8n8.x4.shared.b16 {%0,%1,%2,%3}, [%4];" \
        : "=r"((r)[0]), "=r"((r)[1]), "=r"((r)[2]), "=r"((r)[3]) : "r"(addr))

static __device__ __forceinline__ void mma16816(float* d, const uint32_t* a,
                                                const uint32_t* b) {
    asm volatile(
        "mma.sync.aligned.m16n8k16.row.col.f32.f16.f16.f32 "
        "{%0,%1,%2,%3}, {%4,%5,%6,%7}, {%8,%9}, {%0,%1,%2,%3};"
        : "+f"(d[0]), "+f"(d[1]), "+f"(d[2]), "+f"(d[3])
        : "r"(a[0]), "r"(a[1]), "r"(a[2]), "r"(a[3]), "r"(b[0]), "r"(b[1]));
}

__global__ void __launch_bounds__(THREADS, 1)
vq_fused(const float* __restrict__ x, const float* __restrict__ cb,
         float* __restrict__ out) {
    extern __shared__ char smem[];
    const uint32_t sb = s2u(smem);
    const int tid  = threadIdx.x;
    const int wid  = tid >> 5, lane = tid & 31;

    // ---- stage full codebook (512 codes) as fp16 hi/lo, padded rows ----
    {
        const float4* cb4 = reinterpret_cast<const float4*>(cb);
#pragma unroll
        for (int i = 0; i < (KCODES * DIM / 4) / THREADS; i++) {   // 32 iters
            int idx = i * THREADS + tid;          // 0..8191
            int kr = idx >> 4, d4 = idx & 15;
            float4 v = cb4[idx];
            __half hh[4], ll[4];
            hh[0] = __float2half_rn(v.x); ll[0] = __float2half_rn(v.x - __half2float(hh[0]));
            hh[1] = __float2half_rn(v.y); ll[1] = __float2half_rn(v.y - __half2float(hh[1]));
            hh[2] = __float2half_rn(v.z); ll[2] = __float2half_rn(v.z - __half2float(hh[2]));
            hh[3] = __float2half_rn(v.w); ll[3] = __float2half_rn(v.w - __half2float(hh[3]));
            uint32_t off = kr * ROWB + d4 * 8;
            *(uint2*)(smem + OFF_BHI + off) = *(const uint2*)hh;
            *(uint2*)(smem + OFF_BLO + off) = *(const uint2*)ll;
        }
        // e2: each thread computes 0.5*||code_k||^2 for 2 codes
#pragma unroll
        for (int q = 0; q < 2; q++) {
            int k = q * THREADS + tid;
            const float4* row = reinterpret_cast<const float4*>(cb + k * DIM);
            float s = 0.f;
#pragma unroll
            for (int j = 0; j < DIM / 4; j++) {
                float4 v = row[j];
                s = fmaf(v.x, v.x, s);
                s = fmaf(v.y, v.y, s);
                s = fmaf(v.z, v.z, s);
                s = fmaf(v.w, v.w, s);
            }
            ((float*)(smem + OFF_E2))[k] = 0.5f * s;
        }
    }
    __syncthreads();

    const float* se2 = (const float*)(smem + OFF_E2);
    int* kwin = (int*)(smem + OFF_KW);
    const int R0 = wid * 32;   // warp's pixel-row base (32 rows, 2 sub-tiles)

    for (int t = blockIdx.x; t < NTILES; t += GRID) {
        const int P0  = t * TILE_M;
        const int b   = P0 >> 10;
        const int nl0 = P0 & (HW - 1);
        const float* src = x + (size_t)b * DIM * HW + nl0;

        // ---- stage A tile (256 px x 64 d): thread = one pixel row ----
        {
            const int row = tid;
#pragma unroll
            for (int blk = 0; blk < 8; blk++) {
                __half hh[8], ll[8];
#pragma unroll
                for (int j = 0; j < 8; j++) {
                    float v = src[(size_t)(blk * 8 + j) * HW + row];
                    hh[j] = __float2half_rn(v);
                    ll[j] = __float2half_rn(v - __half2float(hh[j]));
                }
                uint32_t off = row * ROWB + (blk * 8) * 2;
                *(uint4*)(smem + OFF_AHI + off) = *(const uint4*)hh;
                *(uint4*)(smem + OFF_ALO + off) = *(const uint4*)ll;
            }
        }
        __syncthreads();

        float best[2][2] = {{3.4e38f, 3.4e38f}, {3.4e38f, 3.4e38f}};
        int   bidx[2][2] = {{0, 0}, {0, 0}};

        // A ldmatrix addr per sub-tile
        uint32_t aoff[2];
#pragma unroll
        for (int s = 0; s < 2; s++)
            aoff[s] = (R0 + s * 16 + (lane & 15)) * ROWB + (lane >> 4) * 16;
        const uint32_t boff_lane = (lane & 7) * ROWB + (lane >> 3) * 16;

        for (int c0 = 0; c0 < KCODES; c0 += 64) {     // 8 chunks of 64 codes
            float acc[2][8][4];
#pragma unroll
            for (int s = 0; s < 2; s++)
#pragma unroll
                for (int nt = 0; nt < 8; nt++)
#pragma unroll
                    for (int j = 0; j < 4; j++) acc[s][nt][j] = 0.f;

#pragma unroll
            for (int kp = 0; kp < 2; kp++) {          // pairs of k-steps
                uint32_t ah[2][2][4], al[2][2][4];
#pragma unroll
                for (int s = 0; s < 2; s++)
#pragma unroll
                    for (int ks = 0; ks < 2; ks++) {
                        uint32_t q = (kp * 2 + ks) * 32;  // 16 dims = 32B
                        LDSM_X4(ah[s][ks], sb + OFF_AHI + aoff[s] + q);
                        LDSM_X4(al[s][ks], sb + OFF_ALO + aoff[s] + q);
                    }
#pragma unroll
                for (int nt = 0; nt < 8; nt++) {
                    uint32_t bb = (c0 + nt * 8) * ROWB + kp * 64 + boff_lane;
                    uint32_t bh[4], bl[4];
                    LDSM_X4(bh, sb + OFF_BHI + bb);
                    LDSM_X4(bl, sb + OFF_BLO + bb);
#pragma unroll
                    for (int s = 0; s < 2; s++) {
                        mma16816(acc[s][nt], ah[s][0], bh + 0);
                        mma16816(acc[s][nt], ah[s][1], bh + 2);
                        mma16816(acc[s][nt], ah[s][0], bl + 0);
                        mma16816(acc[s][nt], ah[s][1], bl + 2);
                        mma16816(acc[s][nt], al[s][0], bh + 0);
                        mma16816(acc[s][nt], al[s][1], bh + 2);
                    }
                }
            }

            // score: dist/2 = 0.5*||e||^2 - dot
#pragma unroll
            for (int nt = 0; nt < 8; nt++) {
                int cbase = c0 + nt * 8 + (lane & 3) * 2;
#pragma unroll
                for (int j = 0; j < 2; j++) {
                    float e = se2[cbase + j];
                    int   c = cbase + j;
#pragma unroll
                    for (int s = 0; s < 2; s++) {
                        float s0 = e - acc[s][nt][j];
                        float s1 = e - acc[s][nt][2 + j];
                        if (s0 < best[s][0]) { best[s][0] = s0; bidx[s][0] = c; }
                        if (s1 < best[s][1]) { best[s][1] = s1; bidx[s][1] = c; }
                    }
                }
            }
        }

        // reduce across the 4 lanes sharing each row (lane&3 groups)
#pragma unroll
        for (int s = 0; s < 2; s++)
#pragma unroll
            for (int j = 0; j < 2; j++) {
                float bv = best[s][j];
                int   bk = bidx[s][j];
#pragma unroll
                for (int m = 1; m <= 2; m <<= 1) {
                    float ov = __shfl_xor_sync(0xffffffffu, bv, m);
                    int   ok = __shfl_xor_sync(0xffffffffu, bk, m);
                    if (ov < bv || (ov == bv && ok < bk)) { bv = ov; bk = ok; }
                }
                best[s][j] = bv;
                bidx[s][j] = bk;
            }
        if ((lane & 3) == 0) {
#pragma unroll
            for (int s = 0; s < 2; s++) {
                kwin[R0 + s * 16 + (lane >> 2)]     = bidx[s][0];
                kwin[R0 + s * 16 + (lane >> 2) + 8] = bidx[s][1];
            }
        }
        __syncthreads();

        // ---- epilogue: gather winner from smem B (hi+lo), write output ----
        {
            const int px = tid;                 // one pixel per thread
            const int k  = kwin[px];
            const char* bhp = smem + OFF_BHI + k * ROWB;
            const char* blp = smem + OFF_BLO + k * ROWB;
            float* ob = out + (size_t)b * DIM * HW + nl0 + px;
#pragma unroll
            for (int j = 0; j < 8; j++) {
                uint4 H = *(const uint4*)(bhp + j * 16);
                uint4 L = *(const uint4*)(blp + j * 16);
                const uint32_t* Hw = &H.x;
                const uint32_t* Lw = &L.x;
#pragma unroll
                for (int e = 0; e < 4; e++) {
                    __half2 h2 = *reinterpret_cast<const __half2*>(&Hw[e]);
                    __half2 l2 = *reinterpret_cast<const __half2*>(&Lw[e]);
                    float v0 = __half2float(__low2half(h2))  + __half2float(__low2half(l2));
                    float v1 = __half2float(__high2half(h2)) + __half2float(__high2half(l2));
                    ob[(size_t)(j * 8 + 2 * e)     * HW] = v0;
                    ob[(size_t)(j * 8 + 2 * e + 1) * HW] = v1;
                }
            }
        }
        // next iteration's A-stage writes A (disjoint from B/kwin reads above);
        // its trailing __syncthreads orders everything before kwin is rewritten
    }
}

extern "C" void kernel_launch(void* const* d_in, const int* in_sizes, int n_in,
                              void* d_out, int out_size) {
    const float* x  = (const float*)d_in[0];   // (64, 64, 32, 32) fp32
    const float* cb = (const float*)d_in[1];   // (512, 64) fp32
    float* out = (float*)d_out;

    cudaFuncSetAttribute(vq_fused, cudaFuncAttributeMaxDynamicSharedMemorySize,
                         SMEM_SZ);

    vq_fused<<<GRID, THREADS, SMEM_SZ>>>(x, cb, out);
}

// round 12
// speedup vs baseline: 1.4190x; 1.4190x over previous
#include <cuda_runtime.h>
#include <cuda_fp16.h>
#include <cstdint>

#define NPIX    65536
#define HW      1024
#define DIM     64
#define KCODES  512
#define TILE_M  128          // pixels per tile
#define NTILES  512
#define GRID    148
#define THREADS 512          // 16 warps: 8 M-warps x 2 code-groups

// smem layout; rows padded to 144B (72 halves) -> conflict-free ldmatrix
#define ROWB    144
#define ABUF_SZ (TILE_M * ROWB * 2)          // 36864 (hi at +0, lo at +18432)
#define OFF_BHI (2 * ABUF_SZ)                // 73728
#define OFF_BLO (OFF_BHI + KCODES * ROWB)    // 147456
#define OFF_E2  (OFF_BLO + KCODES * ROWB)    // 221184
#define OFF_RB  (OFF_E2 + KCODES * 4)        // 223232  (rbest [2][128] f32)
#define OFF_RI  (OFF_RB + 2 * TILE_M * 4)    // 224256  (ridx  [2][128] i32)
#define SMEM_SZ (OFF_RI + 2 * TILE_M * 4)    // 225280

static __device__ __forceinline__ uint32_t s2u(const void* p) {
    uint32_t a;
    asm("{ .reg .u64 t; cvta.to.shared.u64 t, %1; cvt.u32.u64 %0, t; }"
        : "=r"(a) : "l"(p));
    return a;
}

#define LDSM_X4(r, addr) \
    asm volatile("ldmatrix.sync.aligned.m8n8.x4.shared.b16 {%0,%1,%2,%3}, [%4];" \
        : "=r"((r)[0]), "=r"((r)[1]), "=r"((r)[2]), "=r"((r)[3]) : "r"(addr))

static __device__ __forceinline__ void mma16816(float* d, const uint32_t* a,
                                                const uint32_t* b) {
    asm volatile(
        "mma.sync.aligned.m16n8k16.row.col.f32.f16.f16.f32 "
        "{%0,%1,%2,%3}, {%4,%5,%6,%7}, {%8,%9}, {%0,%1,%2,%3};"
        : "+f"(d[0]), "+f"(d[1]), "+f"(d[2]), "+f"(d[3])
        : "r"(a[0]), "r"(a[1]), "r"(a[2]), "r"(a[3]), "r"(b[0]), "r"(b[1]));
}

// stage 128-px x 64-dim A tile into buffer buf (fp16 hi/lo)
static __device__ __forceinline__ void stage_A(char* smem, int buf,
                                               const float* src, int tid) {
    const int px = tid & 127;
    const int d0 = (tid >> 7) * 16;      // 16 dims per thread
    char* base = smem + buf * ABUF_SZ;
#pragma unroll
    for (int blk = 0; blk < 2; blk++) {
        __half hh[8], ll[8];
#pragma unroll
        for (int j = 0; j < 8; j++) {
            float v = src[(size_t)(d0 + blk * 8 + j) * HW + px];
            hh[j] = __float2half_rn(v);
            ll[j] = __float2half_rn(v - __half2float(hh[j]));
        }
        uint32_t off = px * ROWB + (d0 + blk * 8) * 2;
        *(uint4*)(base + off) = *(const uint4*)hh;
        *(uint4*)(base + TILE_M * ROWB + off) = *(const uint4*)ll;
    }
}

__global__ void __launch_bounds__(THREADS, 1)
vq_fused(const float* __restrict__ x, const float* __restrict__ cb,
         float* __restrict__ out) {
    extern __shared__ char smem[];
    const uint32_t sb = s2u(smem);
    const int tid  = threadIdx.x;
    const int wid  = tid >> 5, lane = tid & 31;
    const int MW   = wid & 7;            // M-warp: rows MW*16..+15
    const int CG   = wid >> 3;           // code group: 0 or 1
    const int kbase = CG * 256;

    // ---- stage full codebook (512 codes) as fp16 hi/lo ----
    {
        const float4* cb4 = reinterpret_cast<const float4*>(cb);
#pragma unroll
        for (int i = 0; i < (KCODES * DIM / 4) / THREADS; i++) {   // 16 iters
            int idx = i * THREADS + tid;
            int kr = idx >> 4, d4 = idx & 15;
            float4 v = cb4[idx];
            __half hh[4], ll[4];
            hh[0] = __float2half_rn(v.x); ll[0] = __float2half_rn(v.x - __half2float(hh[0]));
            hh[1] = __float2half_rn(v.y); ll[1] = __float2half_rn(v.y - __half2float(hh[1]));
            hh[2] = __float2half_rn(v.z); ll[2] = __float2half_rn(v.z - __half2float(hh[2]));
            hh[3] = __float2half_rn(v.w); ll[3] = __float2half_rn(v.w - __half2float(hh[3]));
            uint32_t off = kr * ROWB + d4 * 8;
            *(uint2*)(smem + OFF_BHI + off) = *(const uint2*)hh;
            *(uint2*)(smem + OFF_BLO + off) = *(const uint2*)ll;
        }
        // e2: one code per thread
        const float4* row = reinterpret_cast<const float4*>(cb + tid * DIM);
        float s = 0.f;
#pragma unroll
        for (int j = 0; j < DIM / 4; j++) {
            float4 v = row[j];
            s = fmaf(v.x, v.x, s);
            s = fmaf(v.y, v.y, s);
            s = fmaf(v.z, v.z, s);
            s = fmaf(v.w, v.w, s);
        }
        ((float*)(smem + OFF_E2))[tid] = 0.5f * s;
    }

    const float* se2 = (const float*)(smem + OFF_E2);
    float* rb = (float*)(smem + OFF_RB);
    int*   ri = (int*)(smem + OFF_RI);

    int t = blockIdx.x;
    stage_A(smem, 0, x + (size_t)((t * TILE_M) >> 10) * DIM * HW
                       + ((t * TILE_M) & (HW - 1)), tid);
    __syncthreads();
    int cur = 0;

    const uint32_t aoff_lane = (MW * 16 + (lane & 15)) * ROWB + (lane >> 4) * 16;
    const uint32_t boff_lane = (lane & 7) * ROWB + (lane >> 3) * 16;

    while (true) {
        const int P0  = t * TILE_M;
        const int b   = P0 >> 10;
        const int nl0 = P0 & (HW - 1);
        const int tn  = t + GRID;

        // prefetch-stage next tile into the other buffer
        if (tn < NTILES) {
            const int Pn = tn * TILE_M;
            stage_A(smem, cur ^ 1,
                    x + (size_t)(Pn >> 10) * DIM * HW + (Pn & (HW - 1)), tid);
        }

        // ---- MMA over this group's 256 codes ----
        float best0 = 3.4e38f, best1 = 3.4e38f;
        int   bi0 = 0, bi1 = 0;
        const uint32_t Ahi = sb + cur * ABUF_SZ + aoff_lane;
        const uint32_t Alo = Ahi + TILE_M * ROWB;

#pragma unroll
        for (int cc = 0; cc < 4; cc++) {              // 4 chunks of 64 codes
            const int c0 = kbase + cc * 64;
            float acc[8][4];
#pragma unroll
            for (int nt = 0; nt < 8; nt++)
#pragma unroll
                for (int j = 0; j < 4; j++) acc[nt][j] = 0.f;

#pragma unroll
            for (int kp = 0; kp < 2; kp++) {
                uint32_t ah[2][4], al[2][4];
#pragma unroll
                for (int ks = 0; ks < 2; ks++) {
                    uint32_t q = (kp * 2 + ks) * 32;
                    LDSM_X4(ah[ks], Ahi + q);
                    LDSM_X4(al[ks], Alo + q);
                }
#pragma unroll
                for (int nt = 0; nt < 8; nt++) {
                    uint32_t bb = (c0 + nt * 8) * ROWB + kp * 64 + boff_lane;
                    uint32_t bh[4], bl[4];
                    LDSM_X4(bh, sb + OFF_BHI + bb);
                    LDSM_X4(bl, sb + OFF_BLO + bb);
                    mma16816(acc[nt], ah[0], bh + 0);
                    mma16816(acc[nt], ah[1], bh + 2);
                    mma16816(acc[nt], ah[0], bl + 0);
                    mma16816(acc[nt], ah[1], bl + 2);
                    mma16816(acc[nt], al[0], bh + 0);
                    mma16816(acc[nt], al[1], bh + 2);
                }
            }
#pragma unroll
            for (int nt = 0; nt < 8; nt++) {
                int cbase = c0 + nt * 8 + (lane & 3) * 2;
#pragma unroll
                for (int j = 0; j < 2; j++) {
                    float e = se2[cbase + j];
                    int   c = cbase + j;
                    float s0 = e - acc[nt][j];
                    float s1 = e - acc[nt][2 + j];
                    if (s0 < best0) { best0 = s0; bi0 = c; }
                    if (s1 < best1) { best1 = s1; bi1 = c; }
                }
            }
        }

        // reduce across the 4 lanes sharing each row
#pragma unroll
        for (int m = 1; m <= 2; m <<= 1) {
            float o0 = __shfl_xor_sync(0xffffffffu, best0, m);
            int   i0 = __shfl_xor_sync(0xffffffffu, bi0, m);
            float o1 = __shfl_xor_sync(0xffffffffu, best1, m);
            int   i1 = __shfl_xor_sync(0xffffffffu, bi1, m);
            if (o0 < best0 || (o0 == best0 && i0 < bi0)) { best0 = o0; bi0 = i0; }
            if (o1 < best1 || (o1 == best1 && i1 < bi1)) { best1 = o1; bi1 = i1; }
        }
        if ((lane & 3) == 0) {
            int pr = MW * 16 + (lane >> 2);
            rb[CG * TILE_M + pr]     = best0;
            ri[CG * TILE_M + pr]     = bi0;
            rb[CG * TILE_M + pr + 8] = best1;
            ri[CG * TILE_M + pr + 8] = bi1;
        }
        __syncthreads();

        // ---- epilogue: pick group winner, gather from smem B, write out ----
        {
            const int px = tid & 127;
            const int qh = tid >> 7;           // dim quarter 0..3
            float b0 = rb[px], b1 = rb[TILE_M + px];
            int k = (b0 <= b1) ? ri[px] : ri[TILE_M + px];
            const char* bhp = smem + OFF_BHI + k * ROWB + qh * 32;
            const char* blp = smem + OFF_BLO + k * ROWB + qh * 32;
            float* ob = out + (size_t)b * DIM * HW + nl0 + px
                            + (size_t)(qh * 16) * HW;
#pragma unroll
            for (int j = 0; j < 2; j++) {
                uint4 H = *(const uint4*)(bhp + j * 16);
                uint4 L = *(const uint4*)(blp + j * 16);
                const uint32_t* Hw = &H.x;
                const uint32_t* Lw = &L.x;
#pragma unroll
                for (int e = 0; e < 4; e++) {
                    __half2 h2 = *reinterpret_cast<const __half2*>(&Hw[e]);
                    __half2 l2 = *reinterpret_cast<const __half2*>(&Lw[e]);
                    float v0 = __half2float(__low2half(h2))  + __half2float(__low2half(l2));
                    float v1 = __half2float(__high2half(h2)) + __half2float(__high2half(l2));
                    ob[(size_t)(j * 8 + 2 * e)     * HW] = v0;
                    ob[(size_t)(j * 8 + 2 * e + 1) * HW] = v1;
                }
            }
        }

        cur ^= 1;
        t = tn;
        if (t >= NTILES) break;
        __syncthreads();   // rb/ri reusable; A[cur^1] fully read
    }
}

extern "C" void kernel_launch(void* const* d_in, const int* in_sizes, int n_in,
                              void* d_out, int out_size) {
    const float* x  = (const float*)d_in[0];   // (64, 64, 32, 32) fp32
    const float* cb = (const float*)d_in[1];   // (512, 64) fp32
    float* out = (float*)d_out;

    cudaFuncSetAttribute(vq_fused, cudaFuncAttributeMaxDynamicSharedMemorySize,
                         SMEM_SZ);

    vq_fused<<<GRID, THREADS, SMEM_SZ>>>(x, cb, out);
}